// round 12
// baseline (speedup 1.0000x reference)
#include <cuda_runtime.h>
#include <cuda_bf16.h>
#include <cstdint>

// Problem constants
#define NN 25000
#define PP 400000
#define FF 224
#define KK 32
#define THH 7
#define DV 56
#define NORD 15

// gemm tiling
#define GM 64          // edges per gemm CTA (PP/GM = 6250 exact)
#define GT 256         // gemm threads
#define HP2 72         // Hs hi/lo pitch (u32): bank (8r+2c)%32 -> 2-wavefront v2 loads
#define WP2 464        // W2s hi/lo pitch (u32): bank (16k+2n)%32 -> 2-wavefront v2 loads
#define QP 228         // qs/ks pitch (floats): bank (4r+c)%32 -> 2-way max

#define SEPB 32        // scatter edges per block

// -------- static device scratch (no allocation allowed) --------
__device__ float g_q[NN * FF];
__device__ float g_k[NN * FF];
__device__ float g_v[NN * FF];
__device__ float g_H[(size_t)PP * FF];
__device__ float g_alpha[(size_t)PP * THH];
__device__ uint2 g_W2hl[FF * FF];   // tf32 hi/lo of W2cat

__device__ __forceinline__ float silu_f(float x) {
    return x / (1.0f + __expf(-x));
}

__device__ __forceinline__ uint32_t f2tf32(float x) {
    uint32_t r;
    asm("cvt.rna.tf32.f32 %0, %1;" : "=r"(r) : "f"(x));
    return r;
}

__device__ __forceinline__ void mma_tf32(float* d, const uint32_t* a, const uint32_t* b) {
    asm volatile(
        "mma.sync.aligned.m16n8k8.row.col.f32.tf32.tf32.f32 "
        "{%0,%1,%2,%3}, {%4,%5,%6,%7}, {%8,%9}, {%0,%1,%2,%3};\n"
        : "+f"(d[0]), "+f"(d[1]), "+f"(d[2]), "+f"(d[3])
        : "r"(a[0]), "r"(a[1]), "r"(a[2]), "r"(a[3]), "r"(b[0]), "r"(b[1]));
}

// -------- node: q,k,v precompute + output zeroing + W2 hi/lo prep --------
__global__ __launch_bounds__(224) void node_kernel(
    const float* __restrict__ x,
    const float* __restrict__ Wq,
    const float* __restrict__ Wk,
    const float* __restrict__ Wv,
    const float* __restrict__ W2r,
    const float* __restrict__ W2s_,
    float* __restrict__ out_x,
    float* __restrict__ out_ev)
{
    __shared__ float xs[FF];
    int n = blockIdx.x;
    int f = threadIdx.x;

    // one-time-per-call W2cat -> tf32 hi/lo (first 224 CTAs, one row each)
    if (n < FF) {
        float v = (n < 112) ? W2r[n * FF + f] : W2s_[(n - 112) * FF + f];
        uint32_t hi = f2tf32(v);
        uint32_t lo = f2tf32(v - __uint_as_float(hi));
        g_W2hl[n * FF + f] = make_uint2(hi, lo);
    }

    xs[f] = x[n * FF + f];
    out_x[(size_t)n * FF + f] = 0.0f;
    if (f < NORD) out_ev[(size_t)n * NORD + f] = 0.0f;
    __syncthreads();

    {
        int t = f >> 5;
        int i = f & 31;
        const float* wq = Wq + (t * 32 + i) * 32;
        const float* wk = Wk + (t * 32 + i) * 32;
        const float* xb = xs + t * 32;
        float aq = 0.f, ak = 0.f;
#pragma unroll
        for (int j = 0; j < 32; j++) {
            float xv = xb[j];
            aq = fmaf(__ldg(&wq[j]), xv, aq);
            ak = fmaf(__ldg(&wk[j]), xv, ak);
        }
        g_q[n * FF + f] = silu_f(aq);
        g_k[n * FF + f] = silu_f(ak);
    }
    {
        int h = f / DV;
        int i = f % DV;
        const float* wv = Wv + (h * DV + i) * DV;
        const float* xb = xs + h * DV;
        float av = 0.f;
#pragma unroll 8
        for (int j = 0; j < DV; j++) av = fmaf(__ldg(&wv[j]), xb[j], av);
        g_v[n * FF + f] = av;
    }
}

// -------- h: edge MLP hidden activations -> g_H[P][224] --------
__global__ __launch_bounds__(224) void h_kernel(
    const float* __restrict__ rbf,
    const float* __restrict__ cut,
    const int*   __restrict__ idx_i,
    const int*   __restrict__ idx_j,
    const float* __restrict__ ev,
    const float* __restrict__ W1r, const float* __restrict__ b1r,
    const float* __restrict__ W1s, const float* __restrict__ b1s)
{
    __shared__ float rbfc[GM][KK];
    __shared__ float con_s[GM][3];
    __shared__ float cut_s[GM];

    const int tid = threadIdx.x;
    const int p0  = blockIdx.x * GM;

    if (tid < GM) cut_s[tid] = cut[p0 + tid];
    __syncthreads();

    for (int idx = tid; idx < GM * KK; idx += 224) {
        int e = idx >> 5, kk = idx & 31;
        rbfc[e][kk] = rbf[(size_t)(p0 + e) * KK + kk] * cut_s[e];
    }
    if (tid < GM) {
        int e = tid;
        const float* evi = ev + (size_t)idx_i[p0 + e] * NORD;
        const float* evj = ev + (size_t)idx_j[p0 + e] * NORD;
        float c0 = 0.f, c1 = 0.f, c2 = 0.f;
#pragma unroll
        for (int o = 0; o < 3; o++)  { float d = __ldg(&evj[o]) - __ldg(&evi[o]); c0 = fmaf(d, d, c0); }
#pragma unroll
        for (int o = 3; o < 8; o++)  { float d = __ldg(&evj[o]) - __ldg(&evi[o]); c1 = fmaf(d, d, c1); }
#pragma unroll
        for (int o = 8; o < 15; o++) { float d = __ldg(&evj[o]) - __ldg(&evi[o]); c2 = fmaf(d, d, c2); }
        con_s[e][0] = c0; con_s[e][1] = c1; con_s[e][2] = c2;
    }
    __syncthreads();

    const int cH = tid % 112;
    const int eBase = (tid >= 112) ? 1 : 0;
    float w1rr[32];
#pragma unroll
    for (int kk = 0; kk < 32; kk++) w1rr[kk] = __ldg(&W1r[kk * 112 + cH]);
    const float w1s0 = __ldg(&W1s[cH]);
    const float w1s1 = __ldg(&W1s[112 + cH]);
    const float w1s2 = __ldg(&W1s[224 + cH]);
    const float b1rc = __ldg(&b1r[cH]);
    const float b1sc = __ldg(&b1s[cH]);

#pragma unroll 4
    for (int k2 = 0; k2 < GM / 2; k2++) {
        const int e = 2 * k2 + eBase;
        const float4* r4 = (const float4*)&rbfc[e][0];
        float a1 = b1rc;
#pragma unroll
        for (int q = 0; q < 8; q++) {
            float4 rv = r4[q];
            a1 = fmaf(rv.x, w1rr[4 * q + 0], a1);
            a1 = fmaf(rv.y, w1rr[4 * q + 1], a1);
            a1 = fmaf(rv.z, w1rr[4 * q + 2], a1);
            a1 = fmaf(rv.w, w1rr[4 * q + 3], a1);
        }
        float a2 = b1sc;
        a2 = fmaf(con_s[e][0], w1s0, a2);
        a2 = fmaf(con_s[e][1], w1s1, a2);
        a2 = fmaf(con_s[e][2], w1s2, a2);
        size_t row = (size_t)(p0 + e) * FF;
        g_H[row + cH]       = silu_f(a1);
        g_H[row + 112 + cH] = silu_f(a2);
    }
}

// -------- gemm: alpha[P,7] via 3xTF32 mma.sync --------
// CTA: M=64 edges x N=224 x K=224.  8 warps as 2(M) x 4(N); warp tile 32x56.
extern "C" __global__ void __launch_bounds__(GT) gemm_alpha_kernel(
    const int*   __restrict__ idx_i,
    const int*   __restrict__ idx_j,
    const float* __restrict__ cut,
    const float* __restrict__ b2r,
    const float* __restrict__ b2s)
{
    extern __shared__ uint32_t smg[];
    uint32_t* HsA = smg;                 // [GM][HP2]  hi/lo interleaved
    uint32_t* WsB = smg + GM * HP2;      // [32][WP2]

    __shared__ int   ii_s[GM], jj_s[GM];
    __shared__ float cut_s[GM];
    __shared__ float alpha_sm[GM][8];

    const int tid  = threadIdx.x;
    const int lane = tid & 31;
    const int wid  = tid >> 5;
    const int warpM = wid & 1;           // 0..1
    const int warpN = wid >> 1;          // 0..3
    const int p0 = blockIdx.x * GM;

    if (tid < GM) {
        ii_s[tid]  = idx_i[p0 + tid];
        jj_s[tid]  = idx_j[p0 + tid];
        cut_s[tid] = cut[p0 + tid];
    }
    for (int i = tid; i < GM * 8; i += GT) ((float*)alpha_sm)[i] = 0.0f;

    // D init with combined bias (bias contributes  sum_f bias[f]*G[e,f]  to alpha)
    float d[2][7][4];
#pragma unroll
    for (int nb = 0; nb < 7; nb++) {
        int colb = warpN * 56 + nb * 8 + 2 * (lane & 3);
        float bz0 = __ldg(&b2r[colb])     + __ldg(&b2s[colb]);
        float bz1 = __ldg(&b2r[colb + 1]) + __ldg(&b2s[colb + 1]);
        d[0][nb][0] = bz0; d[0][nb][1] = bz1; d[0][nb][2] = bz0; d[0][nb][3] = bz1;
        d[1][nb][0] = bz0; d[1][nb][1] = bz1; d[1][nb][2] = bz0; d[1][nb][3] = bz1;
    }

#pragma unroll 1
    for (int kc = 0; kc < 7; kc++) {
        __syncthreads();
        // stage H chunk [64 x 32] -> hi/lo interleaved
        for (int i = tid; i < GM * 16; i += GT) {
            int r = i >> 4, c2 = i & 15;
            float2 v = *(const float2*)(g_H + (size_t)(p0 + r) * FF + kc * 32 + c2 * 2);
            uint32_t h0 = f2tf32(v.x);
            uint32_t l0 = f2tf32(v.x - __uint_as_float(h0));
            uint32_t h1 = f2tf32(v.y);
            uint32_t l1 = f2tf32(v.y - __uint_as_float(h1));
            *(uint4*)(HsA + r * HP2 + c2 * 4) = make_uint4(h0, l0, h1, l1);
        }
        // stage W2 chunk [32 x 224] (already hi/lo in gmem)
        for (int i = tid; i < 32 * 112; i += GT) {
            int kr = i / 112, f2i = i % 112;
            uint4 v = *(const uint4*)(g_W2hl + (size_t)(kc * 32 + kr) * FF + f2i * 2);
            *(uint4*)(WsB + kr * WP2 + f2i * 4) = v;
        }
        __syncthreads();

#pragma unroll
        for (int ks8 = 0; ks8 < 4; ks8++) {
            const int k0 = ks8 * 8;
            uint32_t ahi[2][4], alo[2][4];
#pragma unroll
            for (int mb = 0; mb < 2; mb++) {
                int rb = warpM * 32 + mb * 16 + (lane >> 2);
                int cb = k0 + (lane & 3);
                uint2 v;
                v = *(const uint2*)(HsA + rb * HP2 + cb * 2);             ahi[mb][0] = v.x; alo[mb][0] = v.y;
                v = *(const uint2*)(HsA + (rb + 8) * HP2 + cb * 2);       ahi[mb][1] = v.x; alo[mb][1] = v.y;
                v = *(const uint2*)(HsA + rb * HP2 + (cb + 4) * 2);       ahi[mb][2] = v.x; alo[mb][2] = v.y;
                v = *(const uint2*)(HsA + (rb + 8) * HP2 + (cb + 4) * 2); ahi[mb][3] = v.x; alo[mb][3] = v.y;
            }
            uint32_t bhi[7][2], blo[7][2];
#pragma unroll
            for (int nb = 0; nb < 7; nb++) {
                int n  = warpN * 56 + nb * 8 + (lane >> 2);
                int kr = k0 + (lane & 3);
                uint2 v;
                v = *(const uint2*)(WsB + kr * WP2 + n * 2);       bhi[nb][0] = v.x; blo[nb][0] = v.y;
                v = *(const uint2*)(WsB + (kr + 4) * WP2 + n * 2); bhi[nb][1] = v.x; blo[nb][1] = v.y;
            }
#pragma unroll
            for (int mb = 0; mb < 2; mb++)
#pragma unroll
                for (int nb = 0; nb < 7; nb++) {
                    mma_tf32(d[mb][nb], ahi[mb], bhi[nb]);
                    mma_tf32(d[mb][nb], ahi[mb], blo[nb]);
                    mma_tf32(d[mb][nb], alo[mb], bhi[nb]);
                }
        }
    }

    // ---- epilogue: G-gating + head reduction ----
    __syncthreads();
    float* qs = (float*)smg;             // [GM][QP]
    float* ks = (float*)smg + GM * QP;   // [GM][QP]
    for (int i = tid; i < GM * 56; i += GT) {
        int r = i / 56, f4 = i % 56;
        *(float4*)(qs + r * QP + f4 * 4) = *(const float4*)(g_q + (size_t)ii_s[r] * FF + f4 * 4);
        *(float4*)(ks + r * QP + f4 * 4) = *(const float4*)(g_k + (size_t)jj_s[r] * FF + f4 * 4);
    }
    __syncthreads();

#pragma unroll
    for (int mb = 0; mb < 2; mb++) {
        int r0 = warpM * 32 + mb * 16 + (lane >> 2);
        int r1 = r0 + 8;
#pragma unroll
        for (int nb = 0; nb < 7; nb++) {
            int colb = warpN * 56 + nb * 8 + 2 * (lane & 3);
            int h = colb >> 5;
            float g00 = qs[r0 * QP + colb]     * ks[r0 * QP + colb];
            float g01 = qs[r0 * QP + colb + 1] * ks[r0 * QP + colb + 1];
            float g10 = qs[r1 * QP + colb]     * ks[r1 * QP + colb];
            float g11 = qs[r1 * QP + colb + 1] * ks[r1 * QP + colb + 1];
            atomicAdd(&alpha_sm[r0][h], fmaf(d[mb][nb][0], g00, d[mb][nb][1] * g01));
            atomicAdd(&alpha_sm[r1][h], fmaf(d[mb][nb][2], g10, d[mb][nb][3] * g11));
        }
    }
    __syncthreads();

    for (int i = tid; i < GM * THH; i += GT) {
        int e = i / THH, h = i % THH;
        g_alpha[(size_t)(p0 + e) * THH + h] = alpha_sm[e][h] * cut_s[e];
    }
}

// -------- scatter: out_x and out_ev from alpha (cut folded in) --------
__global__ __launch_bounds__(224) void scatter_kernel(
    const int*   __restrict__ idx_i,
    const int*   __restrict__ idx_j,
    const float* __restrict__ ylm,
    float* __restrict__ out_x,
    float* __restrict__ out_ev)
{
    __shared__ float a_sm[SEPB][8];
    __shared__ float ylm_s[SEPB][NORD];
    __shared__ int   ii_s[SEPB], jj_s[SEPB];

    const int tid = threadIdx.x;
    const int p0  = blockIdx.x * SEPB;

    if (tid < SEPB) {
        ii_s[tid] = idx_i[p0 + tid];
        jj_s[tid] = idx_j[p0 + tid];
    }
    if (tid < SEPB * THH) {
        int e = tid / THH, h = tid % THH;
        a_sm[e][h] = g_alpha[(size_t)(p0 + e) * THH + h];
    }
    for (int idx = tid; idx < SEPB * NORD; idx += 224) {
        int e = idx / NORD, o = idx % NORD;
        ylm_s[e][o] = ylm[(size_t)(p0 + e) * NORD + o];
    }
    __syncthreads();

    {
        int f = tid;
        int hh = f / DV;
        float run = 0.f;
        int iprev = ii_s[0];
#pragma unroll 4
        for (int e = 0; e < SEPB; e++) {
            int i = ii_s[e];
            if (i != iprev) {
                atomicAdd(&out_x[(size_t)iprev * FF + f], run);
                run = 0.f; iprev = i;
            }
            run = fmaf(a_sm[e][hh], __ldg(&g_v[(size_t)jj_s[e] * FF + f]), run);
        }
        atomicAdd(&out_x[(size_t)iprev * FF + f], run);
    }
    if (tid < NORD) {
        int o  = tid;
        int hh = (o < 3) ? 4 : ((o < 8) ? 5 : 6);
        float run = 0.f;
        int iprev = ii_s[0];
        for (int e = 0; e < SEPB; e++) {
            int i = ii_s[e];
            if (i != iprev) {
                atomicAdd(&out_ev[(size_t)iprev * NORD + o], run);
                run = 0.f; iprev = i;
            }
            run = fmaf(a_sm[e][hh], ylm_s[e][o], run);
        }
        atomicAdd(&out_ev[(size_t)iprev * NORD + o], run);
    }
}

extern "C" void kernel_launch(void* const* d_in, const int* in_sizes, int n_in,
                              void* d_out, int out_size) {
    const float* x     = (const float*)d_in[0];
    const float* ev    = (const float*)d_in[1];
    const float* rbf   = (const float*)d_in[2];
    const float* ylm   = (const float*)d_in[3];
    const float* cut   = (const float*)d_in[4];
    const int*   idx_i = (const int*)d_in[5];
    const int*   idx_j = (const int*)d_in[6];
    const float* W1r   = (const float*)d_in[7];
    const float* b1r   = (const float*)d_in[8];
    const float* W2r   = (const float*)d_in[9];
    const float* b2r   = (const float*)d_in[10];
    const float* W1s   = (const float*)d_in[11];
    const float* b1s   = (const float*)d_in[12];
    const float* W2s_  = (const float*)d_in[13];
    const float* b2s   = (const float*)d_in[14];
    const float* Wq    = (const float*)d_in[15];
    const float* Wk    = (const float*)d_in[16];
    const float* Wv    = (const float*)d_in[17];

    float* out    = (float*)d_out;
    float* out_x  = out;                       // [N,224]
    float* out_ev = out + (size_t)NN * FF;     // [N,15]

    // gemm dyn smem: max(phase1 hi/lo tiles, phase2 q/k tiles)
    const int dyn1 = (GM * HP2 + 32 * WP2) * 4;   // 77824
    const int dyn2 = (2 * GM * QP) * 4;           // 116736
    const int dynsmem = dyn1 > dyn2 ? dyn1 : dyn2;
    cudaFuncSetAttribute(gemm_alpha_kernel, cudaFuncAttributeMaxDynamicSharedMemorySize, dynsmem);

    // 1) per-node q,k,v + zero outputs + W2 tf32 prep
    node_kernel<<<NN, 224>>>(x, Wq, Wk, Wv, W2r, W2s_, out_x, out_ev);

    // 2) edge MLP hidden -> g_H
    h_kernel<<<PP / GM, 224>>>(rbf, cut, idx_i, idx_j, ev, W1r, b1r, W1s, b1s);

    // 3) tensor-core trilinear -> g_alpha
    gemm_alpha_kernel<<<PP / GM, GT, dynsmem>>>(idx_i, idx_j, cut, b2r, b2s);

    // 4) scatter
    scatter_kernel<<<PP / SEPB, 224>>>(idx_i, idx_j, ylm, out_x, out_ev);
}

// round 13
// speedup vs baseline: 1.3293x; 1.3293x over previous
#include <cuda_runtime.h>
#include <cuda_bf16.h>

// Problem constants (fixed shapes from reference)
#define NN 25000
#define PP 400000
#define FF 224      // = TF = TH*FH
#define KK 32
#define HH 4
#define THH 7
#define DV 56
#define NORD 15

#define EPB 32     // edges per block
#define TPB 224    // threads per block (edge kernel)
#define HP 36      // Hs row pitch (padded: 4-way max conflict, float4 aligned)

// -------- scratch (static device arrays; no allocation allowed) --------
__device__ float g_q[NN * FF];
__device__ float g_k[NN * FF];
__device__ float g_v[NN * FF];

__device__ __forceinline__ float silu_f(float x) {
    return x / (1.0f + __expf(-x));
}

// -------- per-node q,k,v precompute + output zeroing --------
__global__ __launch_bounds__(224) void node_kernel(
    const float* __restrict__ x,
    const float* __restrict__ Wq,
    const float* __restrict__ Wk,
    const float* __restrict__ Wv,
    float* __restrict__ out_x,
    float* __restrict__ out_ev)
{
    __shared__ float xs[FF];
    int n = blockIdx.x;
    int f = threadIdx.x;
    xs[f] = x[n * FF + f];
    // zero outputs (atomics accumulate into them later)
    out_x[(size_t)n * FF + f] = 0.0f;
    if (f < NORD) out_ev[(size_t)n * NORD + f] = 0.0f;
    __syncthreads();

    // q / k
    {
        int t = f >> 5;
        int i = f & 31;
        const float* wq = Wq + (t * 32 + i) * 32;
        const float* wk = Wk + (t * 32 + i) * 32;
        const float* xb = xs + t * 32;
        float aq = 0.f, ak = 0.f;
#pragma unroll
        for (int j = 0; j < 32; j++) {
            float xv = xb[j];
            aq = fmaf(__ldg(&wq[j]), xv, aq);
            ak = fmaf(__ldg(&wk[j]), xv, ak);
        }
        g_q[n * FF + f] = silu_f(aq);
        g_k[n * FF + f] = silu_f(ak);
    }
    // v
    {
        int h = f / DV;
        int i = f % DV;
        const float* wv = Wv + (h * DV + i) * DV;
        const float* xb = xs + h * DV;
        float av = 0.f;
#pragma unroll 8
        for (int j = 0; j < DV; j++) av = fmaf(__ldg(&wv[j]), xb[j], av);
        g_v[n * FF + f] = av;
    }
}

// -------- edge kernel --------
// dyn smem: Hs [224][HP] only (no W2 staging — W2 read via __ldg from L1/L2)
extern "C" __global__ void __launch_bounds__(TPB, 3) edge_kernel(
    const float* __restrict__ rbf,
    const float* __restrict__ ylm,
    const float* __restrict__ cut,
    const int*   __restrict__ idx_i,
    const int*   __restrict__ idx_j,
    const float* __restrict__ ev,
    const float* __restrict__ W1r, const float* __restrict__ b1r,
    const float* __restrict__ W2r, const float* __restrict__ b2r,
    const float* __restrict__ W1s, const float* __restrict__ b1s,
    const float* __restrict__ W2s, const float* __restrict__ b2s,
    float* __restrict__ out_x, float* __restrict__ out_ev)
{
    extern __shared__ float dyn[];
    float* Hs = dyn;                  // 224 * HP  (c-major, padded)

    __shared__ float rbfc[EPB][KK];
    __shared__ float con_s[EPB][3];
    __shared__ float alpha_s[EPB][THH];
    __shared__ float ylm_s[EPB][NORD];
    __shared__ int   ii_s[EPB], jj_s[EPB];
    __shared__ float cut_s[EPB];

    const int tid = threadIdx.x;
    const int p0  = blockIdx.x * EPB;

    if (tid < EPB) {
        int p = p0 + tid;
        ii_s[tid]  = idx_i[p];
        jj_s[tid]  = idx_j[p];
        cut_s[tid] = cut[p];
    }
    if (tid < EPB * THH) ((float*)alpha_s)[tid] = 0.0f;
    __syncthreads();

    // rbf * cut into smem
    for (int idx = tid; idx < EPB * KK; idx += TPB) {
        int e = idx >> 5, kk = idx & 31;
        rbfc[e][kk] = rbf[(p0 + e) * KK + kk] * cut_s[e];
    }
    // ylm into smem
    for (int idx = tid; idx < EPB * NORD; idx += TPB) {
        int e = idx / NORD, o = idx % NORD;
        ylm_s[e][o] = ylm[(p0 + e) * NORD + o];
    }
    // l0 contraction per edge
    if (tid < EPB) {
        int e = tid;
        const float* evi = ev + (size_t)ii_s[e] * NORD;
        const float* evj = ev + (size_t)jj_s[e] * NORD;
        float c0 = 0.f, c1 = 0.f, c2 = 0.f;
#pragma unroll
        for (int o = 0; o < 3; o++)  { float d = __ldg(&evj[o]) - __ldg(&evi[o]); c0 = fmaf(d, d, c0); }
#pragma unroll
        for (int o = 3; o < 8; o++)  { float d = __ldg(&evj[o]) - __ldg(&evi[o]); c1 = fmaf(d, d, c1); }
#pragma unroll
        for (int o = 8; o < 15; o++) { float d = __ldg(&evj[o]) - __ldg(&evi[o]); c2 = fmaf(d, d, c2); }
        con_s[e][0] = c0; con_s[e][1] = c1; con_s[e][2] = c2;
    }
    __syncthreads();

    // ---- H compute ----
    // Thread owns fixed c = tid % 112; visits 16 edges (e = 2k + (tid>=112)).
    // W1r column hoisted into registers (32 coalesced LDGs).
    {
        const int cH = tid % 112;
        const int eBase = (tid >= 112) ? 1 : 0;
        float w1rr[32];
#pragma unroll
        for (int kk = 0; kk < 32; kk++) w1rr[kk] = __ldg(&W1r[kk * 112 + cH]);
        const float w1s0 = __ldg(&W1s[cH]);
        const float w1s1 = __ldg(&W1s[112 + cH]);
        const float w1s2 = __ldg(&W1s[224 + cH]);
        const float b1rc = __ldg(&b1r[cH]);
        const float b1sc = __ldg(&b1s[cH]);
#pragma unroll 4
        for (int k2 = 0; k2 < 16; k2++) {
            const int e = 2 * k2 + eBase;
            const float4* r4 = (const float4*)&rbfc[e][0];
            float a1 = b1rc;
#pragma unroll
            for (int q = 0; q < 8; q++) {
                float4 rv = r4[q];
                a1 = fmaf(rv.x, w1rr[4 * q + 0], a1);
                a1 = fmaf(rv.y, w1rr[4 * q + 1], a1);
                a1 = fmaf(rv.z, w1rr[4 * q + 2], a1);
                a1 = fmaf(rv.w, w1rr[4 * q + 3], a1);
            }
            float a2 = b1sc;
            a2 = fmaf(con_s[e][0], w1s0, a2);
            a2 = fmaf(con_s[e][1], w1s1, a2);
            a2 = fmaf(con_s[e][2], w1s2, a2);
            Hs[cH * HP + e]         = silu_f(a1);
            Hs[(cH + 112) * HP + e] = silu_f(a2);
        }
    }
    __syncthreads();   // Hs complete — the ONLY barrier before the scatter phase

    // ---- main trilinear: wsum[e, f] = sum_c H[e,c] * W2cat[c,f] ----
    // thread tiling: 8 edge-groups (4 edges) x 28 column-chunks (4 cols + 4 cols@+112)
    // W2 is read directly via __ldg (200KB, L1/L2-resident, fully coalesced:
    // 28 lanes read one contiguous 448B run per row) — no staging, no barriers.
    const int eg    = tid / 28;       // 0..7
    const int chunk = tid % 28;       // 0..27
    const int e0 = eg * 4;
    const int f0 = chunk * 4;         // 0..108
    const int hA = f0 >> 5;           // 0..3
    const int hB = (f0 + 112) >> 5;   // 3..6

    float acc[4][8];
    {
        float b2c[8];
#pragma unroll
        for (int u = 0; u < 4; u++) {
            b2c[u]     = __ldg(&b2r[f0 + u])       + __ldg(&b2s[f0 + u]);
            b2c[4 + u] = __ldg(&b2r[f0 + 112 + u]) + __ldg(&b2s[f0 + 112 + u]);
        }
#pragma unroll
        for (int e = 0; e < 4; e++)
#pragma unroll
            for (int u = 0; u < 8; u++) acc[e][u] = b2c[u];
    }

    // rows c = 0..111 from W2r
    {
        const float* wra = W2r + f0;
        const float* wrb = W2r + f0 + 112;
        const float* hp  = Hs + e0;
#pragma unroll 4
        for (int c = 0; c < 112; c++) {
            float4 w0 = __ldg((const float4*)(wra + c * FF));
            float4 w1 = __ldg((const float4*)(wrb + c * FF));
            float4 h4 = *(const float4*)(hp + c * HP);
            float hv[4] = {h4.x, h4.y, h4.z, h4.w};
#pragma unroll
            for (int e = 0; e < 4; e++) {
                acc[e][0] = fmaf(hv[e], w0.x, acc[e][0]);
                acc[e][1] = fmaf(hv[e], w0.y, acc[e][1]);
                acc[e][2] = fmaf(hv[e], w0.z, acc[e][2]);
                acc[e][3] = fmaf(hv[e], w0.w, acc[e][3]);
                acc[e][4] = fmaf(hv[e], w1.x, acc[e][4]);
                acc[e][5] = fmaf(hv[e], w1.y, acc[e][5]);
                acc[e][6] = fmaf(hv[e], w1.z, acc[e][6]);
                acc[e][7] = fmaf(hv[e], w1.w, acc[e][7]);
            }
        }
    }
    // rows c = 112..223 from W2s
    {
        const float* wsa = W2s + f0;
        const float* wsb = W2s + f0 + 112;
        const float* hp  = Hs + 112 * HP + e0;
#pragma unroll 4
        for (int c = 0; c < 112; c++) {
            float4 w0 = __ldg((const float4*)(wsa + c * FF));
            float4 w1 = __ldg((const float4*)(wsb + c * FF));
            float4 h4 = *(const float4*)(hp + c * HP);
            float hv[4] = {h4.x, h4.y, h4.z, h4.w};
#pragma unroll
            for (int e = 0; e < 4; e++) {
                acc[e][0] = fmaf(hv[e], w0.x, acc[e][0]);
                acc[e][1] = fmaf(hv[e], w0.y, acc[e][1]);
                acc[e][2] = fmaf(hv[e], w0.z, acc[e][2]);
                acc[e][3] = fmaf(hv[e], w0.w, acc[e][3]);
                acc[e][4] = fmaf(hv[e], w1.x, acc[e][4]);
                acc[e][5] = fmaf(hv[e], w1.y, acc[e][5]);
                acc[e][6] = fmaf(hv[e], w1.z, acc[e][6]);
                acc[e][7] = fmaf(hv[e], w1.w, acc[e][7]);
            }
        }
    }

    // ---- apply G = q_i * k_j elementwise, reduce over the 8 owned columns ----
#pragma unroll
    for (int e = 0; e < 4; e++) {
        const size_t ri = (size_t)ii_s[e0 + e] * FF;
        const size_t rj = (size_t)jj_s[e0 + e] * FF;
        float4 qa = *(const float4*)&g_q[ri + f0];
        float4 qb = *(const float4*)&g_q[ri + f0 + 112];
        float4 ka = *(const float4*)&g_k[rj + f0];
        float4 kb = *(const float4*)&g_k[rj + f0 + 112];
        float aA = acc[e][0] * (qa.x * ka.x);
        aA = fmaf(acc[e][1], qa.y * ka.y, aA);
        aA = fmaf(acc[e][2], qa.z * ka.z, aA);
        aA = fmaf(acc[e][3], qa.w * ka.w, aA);
        float aB = acc[e][4] * (qb.x * kb.x);
        aB = fmaf(acc[e][5], qb.y * kb.y, aB);
        aB = fmaf(acc[e][6], qb.z * kb.z, aB);
        aB = fmaf(acc[e][7], qb.w * kb.w, aB);
        atomicAdd(&alpha_s[e0 + e][hA], aA);
        atomicAdd(&alpha_s[e0 + e][hB], aB);
    }
    __syncthreads();

    // ---- scatter x_att: thread f owns output column f; run-length aggregate over sorted i
    {
        int f = tid;                 // 0..223
        int hh = f / DV;             // 0..3
        float run = 0.f;
        int iprev = ii_s[0];
#pragma unroll 4
        for (int e = 0; e < EPB; e++) {
            int i = ii_s[e];
            if (i != iprev) {
                atomicAdd(&out_x[(size_t)iprev * FF + f], run);
                run = 0.f; iprev = i;
            }
            float a = alpha_s[e][hh] * cut_s[e];
            run = fmaf(a, __ldg(&g_v[(size_t)jj_s[e] * FF + f]), run);
        }
        atomicAdd(&out_x[(size_t)iprev * FF + f], run);
    }
    // ---- scatter ev_att
    if (tid < NORD) {
        int o  = tid;
        int hh = (o < 3) ? 4 : ((o < 8) ? 5 : 6);
        float run = 0.f;
        int iprev = ii_s[0];
        for (int e = 0; e < EPB; e++) {
            int i = ii_s[e];
            if (i != iprev) {
                atomicAdd(&out_ev[(size_t)iprev * NORD + o], run);
                run = 0.f; iprev = i;
            }
            run = fmaf(alpha_s[e][hh] * cut_s[e], ylm_s[e][o], run);
        }
        atomicAdd(&out_ev[(size_t)iprev * NORD + o], run);
    }
}

extern "C" void kernel_launch(void* const* d_in, const int* in_sizes, int n_in,
                              void* d_out, int out_size) {
    const float* x     = (const float*)d_in[0];
    const float* ev    = (const float*)d_in[1];
    const float* rbf   = (const float*)d_in[2];
    const float* ylm   = (const float*)d_in[3];
    const float* cut   = (const float*)d_in[4];
    const int*   idx_i = (const int*)d_in[5];
    const int*   idx_j = (const int*)d_in[6];
    const float* W1r   = (const float*)d_in[7];
    const float* b1r   = (const float*)d_in[8];
    const float* W2r   = (const float*)d_in[9];
    const float* b2r   = (const float*)d_in[10];
    const float* W1s   = (const float*)d_in[11];
    const float* b1s   = (const float*)d_in[12];
    const float* W2s   = (const float*)d_in[13];
    const float* b2s   = (const float*)d_in[14];
    const float* Wq    = (const float*)d_in[15];
    const float* Wk    = (const float*)d_in[16];
    const float* Wv    = (const float*)d_in[17];

    float* out    = (float*)d_out;
    float* out_x  = out;                       // [N,224]
    float* out_ev = out + (size_t)NN * FF;     // [N,15]

    const int dynsmem = (FF * HP) * (int)sizeof(float);   // 32256 B
    cudaFuncSetAttribute(edge_kernel, cudaFuncAttributeMaxDynamicSharedMemorySize, dynsmem);

    // 1) per-node q,k,v + zero outputs
    node_kernel<<<NN, 224>>>(x, Wq, Wk, Wv, out_x, out_ev);

    // 2) edges
    edge_kernel<<<PP / EPB, TPB, dynsmem>>>(
        rbf, ylm, cut, idx_i, idx_j, ev,
        W1r, b1r, W2r, b2r, W1s, b1s, W2s, b2s,
        out_x, out_ev);
}

// round 17
// speedup vs baseline: 1.3510x; 1.0163x over previous
#include <cuda_runtime.h>
#include <cuda_bf16.h>

// Problem constants (fixed shapes from reference)
#define NN 25000
#define PP 400000
#define FF 224      // = TF = TH*FH
#define KK 32
#define HH 4
#define THH 7
#define DV 56
#define NORD 15

#define EPB 32     // edges per block
#define TPB 224    // threads per block (edge kernel)
#define HP 36      // Hs row pitch (padded, float4 aligned)

typedef unsigned long long ull;

// -------- scratch (static device arrays; no allocation allowed) --------
__device__ float g_q[NN * FF];
__device__ float g_k[NN * FF];
__device__ float g_v[NN * FF];

__device__ __forceinline__ float silu_f(float x) {
    return x / (1.0f + __expf(-x));
}

// packed f32x2 helpers (sm_103a)
__device__ __forceinline__ void fma2(ull& d, ull a, ull b) {
    asm("fma.rn.f32x2 %0, %1, %2, %0;" : "+l"(d) : "l"(a), "l"(b));
}
__device__ __forceinline__ ull pack2(float x) {
    ull r; asm("mov.b64 %0, {%1, %1};" : "=l"(r) : "f"(x)); return r;
}
__device__ __forceinline__ ull pack_ff(float lo, float hi) {
    ull r; asm("mov.b64 %0, {%1, %2};" : "=l"(r) : "f"(lo), "f"(hi)); return r;
}
__device__ __forceinline__ void unpack_ff(ull v, float& lo, float& hi) {
    asm("mov.b64 {%0, %1}, %2;" : "=f"(lo), "=f"(hi) : "l"(v));
}

// -------- per-node q,k,v precompute + output zeroing --------
__global__ __launch_bounds__(224) void node_kernel(
    const float* __restrict__ x,
    const float* __restrict__ Wq,
    const float* __restrict__ Wk,
    const float* __restrict__ Wv,
    float* __restrict__ out_x,
    float* __restrict__ out_ev)
{
    __shared__ float xs[FF];
    int n = blockIdx.x;
    int f = threadIdx.x;
    xs[f] = x[n * FF + f];
    out_x[(size_t)n * FF + f] = 0.0f;
    if (f < NORD) out_ev[(size_t)n * NORD + f] = 0.0f;
    __syncthreads();

    // q / k
    {
        int t = f >> 5;
        int i = f & 31;
        const float* wq = Wq + (t * 32 + i) * 32;
        const float* wk = Wk + (t * 32 + i) * 32;
        const float* xb = xs + t * 32;
        float aq = 0.f, ak = 0.f;
#pragma unroll
        for (int j = 0; j < 32; j++) {
            float xv = xb[j];
            aq = fmaf(__ldg(&wq[j]), xv, aq);
            ak = fmaf(__ldg(&wk[j]), xv, ak);
        }
        g_q[n * FF + f] = silu_f(aq);
        g_k[n * FF + f] = silu_f(ak);
    }
    // v
    {
        int h = f / DV;
        int i = f % DV;
        const float* wv = Wv + (h * DV + i) * DV;
        const float* xb = xs + h * DV;
        float av = 0.f;
#pragma unroll 8
        for (int j = 0; j < DV; j++) av = fmaf(__ldg(&wv[j]), xb[j], av);
        g_v[n * FF + f] = av;
    }
}

// -------- edge kernel --------
// dyn smem: Hs [224][HP] only (W2 read via __ldg from L1/L2)
extern "C" __global__ void __launch_bounds__(TPB, 3) edge_kernel(
    const float* __restrict__ rbf,
    const float* __restrict__ ylm,
    const float* __restrict__ cut,
    const int*   __restrict__ idx_i,
    const int*   __restrict__ idx_j,
    const float* __restrict__ ev,
    const float* __restrict__ W1r, const float* __restrict__ b1r,
    const float* __restrict__ W2r, const float* __restrict__ b2r,
    const float* __restrict__ W1s, const float* __restrict__ b1s,
    const float* __restrict__ W2s, const float* __restrict__ b2s,
    float* __restrict__ out_x, float* __restrict__ out_ev)
{
    extern __shared__ float dyn[];
    float* Hs = dyn;                  // 224 * HP  (c-major, padded)

    __shared__ float rbfc[EPB][KK];
    __shared__ float con_s[EPB][3];
    __shared__ float alpha_s[EPB][THH];
    __shared__ float ylm_s[EPB][NORD];
    __shared__ int   ii_s[EPB], jj_s[EPB];
    __shared__ float cut_s[EPB];

    const int tid = threadIdx.x;
    const int p0  = blockIdx.x * EPB;

    if (tid < EPB) {
        int p = p0 + tid;
        ii_s[tid]  = idx_i[p];
        jj_s[tid]  = idx_j[p];
        cut_s[tid] = cut[p];
    }
    if (tid < EPB * THH) ((float*)alpha_s)[tid] = 0.0f;
    __syncthreads();

    // rbf * cut into smem
    for (int idx = tid; idx < EPB * KK; idx += TPB) {
        int e = idx >> 5, kk = idx & 31;
        rbfc[e][kk] = rbf[(p0 + e) * KK + kk] * cut_s[e];
    }
    // ylm into smem
    for (int idx = tid; idx < EPB * NORD; idx += TPB) {
        int e = idx / NORD, o = idx % NORD;
        ylm_s[e][o] = ylm[(p0 + e) * NORD + o];
    }
    // l0 contraction per edge
    if (tid < EPB) {
        int e = tid;
        const float* evi = ev + (size_t)ii_s[e] * NORD;
        const float* evj = ev + (size_t)jj_s[e] * NORD;
        float c0 = 0.f, c1 = 0.f, c2 = 0.f;
#pragma unroll
        for (int o = 0; o < 3; o++)  { float d = __ldg(&evj[o]) - __ldg(&evi[o]); c0 = fmaf(d, d, c0); }
#pragma unroll
        for (int o = 3; o < 8; o++)  { float d = __ldg(&evj[o]) - __ldg(&evi[o]); c1 = fmaf(d, d, c1); }
#pragma unroll
        for (int o = 8; o < 15; o++) { float d = __ldg(&evj[o]) - __ldg(&evi[o]); c2 = fmaf(d, d, c2); }
        con_s[e][0] = c0; con_s[e][1] = c1; con_s[e][2] = c2;
    }
    __syncthreads();

    // ---- H compute ----
    {
        const int cH = tid % 112;
        const int eBase = (tid >= 112) ? 1 : 0;
        float w1rr[32];
#pragma unroll
        for (int kk = 0; kk < 32; kk++) w1rr[kk] = __ldg(&W1r[kk * 112 + cH]);
        const float w1s0 = __ldg(&W1s[cH]);
        const float w1s1 = __ldg(&W1s[112 + cH]);
        const float w1s2 = __ldg(&W1s[224 + cH]);
        const float b1rc = __ldg(&b1r[cH]);
        const float b1sc = __ldg(&b1s[cH]);
#pragma unroll 4
        for (int k2 = 0; k2 < 16; k2++) {
            const int e = 2 * k2 + eBase;
            const float4* r4 = (const float4*)&rbfc[e][0];
            float a1 = b1rc;
#pragma unroll
            for (int q = 0; q < 8; q++) {
                float4 rv = r4[q];
                a1 = fmaf(rv.x, w1rr[4 * q + 0], a1);
                a1 = fmaf(rv.y, w1rr[4 * q + 1], a1);
                a1 = fmaf(rv.z, w1rr[4 * q + 2], a1);
                a1 = fmaf(rv.w, w1rr[4 * q + 3], a1);
            }
            float a2 = b1sc;
            a2 = fmaf(con_s[e][0], w1s0, a2);
            a2 = fmaf(con_s[e][1], w1s1, a2);
            a2 = fmaf(con_s[e][2], w1s2, a2);
            Hs[cH * HP + e]         = silu_f(a1);
            Hs[(cH + 112) * HP + e] = silu_f(a2);
        }
    }
    __syncthreads();   // Hs complete — only barrier before scatter phase

    // ---- main trilinear: wsum[e,f] = sum_c H[e,c] * W2cat[c,f]  (packed f32x2) ----
    // thread tiling: 8 edge-groups (4 edges) x 28 column-chunks (4 cols + 4 cols@+112)
    const int eg    = tid / 28;       // 0..7
    const int chunk = tid % 28;       // 0..27
    const int e0 = eg * 4;
    const int f0 = chunk * 4;         // 0..108
    const int hA = f0 >> 5;           // 0..3
    const int hB = (f0 + 112) >> 5;   // 3..6

    // acc2[e][p]: p=0,1 -> cols (f0,f0+1),(f0+2,f0+3); p=2,3 -> +112 pair cols
    ull acc2[4][4];
    {
        ull bA0 = pack_ff(__ldg(&b2r[f0])     + __ldg(&b2s[f0]),
                          __ldg(&b2r[f0 + 1]) + __ldg(&b2s[f0 + 1]));
        ull bA1 = pack_ff(__ldg(&b2r[f0 + 2]) + __ldg(&b2s[f0 + 2]),
                          __ldg(&b2r[f0 + 3]) + __ldg(&b2s[f0 + 3]));
        ull bB0 = pack_ff(__ldg(&b2r[f0 + 112]) + __ldg(&b2s[f0 + 112]),
                          __ldg(&b2r[f0 + 113]) + __ldg(&b2s[f0 + 113]));
        ull bB1 = pack_ff(__ldg(&b2r[f0 + 114]) + __ldg(&b2s[f0 + 114]),
                          __ldg(&b2r[f0 + 115]) + __ldg(&b2s[f0 + 115]));
#pragma unroll
        for (int e = 0; e < 4; e++) {
            acc2[e][0] = bA0; acc2[e][1] = bA1; acc2[e][2] = bB0; acc2[e][3] = bB1;
        }
    }

    // rows c = 0..111 from W2r
    {
        const float* wra = W2r + f0;
        const float* wrb = W2r + f0 + 112;
        const float* hp  = Hs + e0;
#pragma unroll 4
        for (int c = 0; c < 112; c++) {
            ulonglong2 w0 = __ldg((const ulonglong2*)(wra + c * FF));
            ulonglong2 w1 = __ldg((const ulonglong2*)(wrb + c * FF));
            float4 h4 = *(const float4*)(hp + c * HP);
            ull h2[4] = {pack2(h4.x), pack2(h4.y), pack2(h4.z), pack2(h4.w)};
#pragma unroll
            for (int e = 0; e < 4; e++) {
                fma2(acc2[e][0], h2[e], w0.x);
                fma2(acc2[e][1], h2[e], w0.y);
                fma2(acc2[e][2], h2[e], w1.x);
                fma2(acc2[e][3], h2[e], w1.y);
            }
        }
    }
    // rows c = 112..223 from W2s
    {
        const float* wsa = W2s + f0;
        const float* wsb = W2s + f0 + 112;
        const float* hp  = Hs + 112 * HP + e0;
#pragma unroll 4
        for (int c = 0; c < 112; c++) {
            ulonglong2 w0 = __ldg((const ulonglong2*)(wsa + c * FF));
            ulonglong2 w1 = __ldg((const ulonglong2*)(wsb + c * FF));
            float4 h4 = *(const float4*)(hp + c * HP);
            ull h2[4] = {pack2(h4.x), pack2(h4.y), pack2(h4.z), pack2(h4.w)};
#pragma unroll
            for (int e = 0; e < 4; e++) {
                fma2(acc2[e][0], h2[e], w0.x);
                fma2(acc2[e][1], h2[e], w0.y);
                fma2(acc2[e][2], h2[e], w1.x);
                fma2(acc2[e][3], h2[e], w1.y);
            }
        }
    }

    // ---- apply G = q_i * k_j elementwise, reduce over the 8 owned columns ----
#pragma unroll
    for (int e = 0; e < 4; e++) {
        float a0, a1, a2, a3, a4, a5, a6, a7;
        unpack_ff(acc2[e][0], a0, a1);
        unpack_ff(acc2[e][1], a2, a3);
        unpack_ff(acc2[e][2], a4, a5);
        unpack_ff(acc2[e][3], a6, a7);
        const size_t ri = (size_t)ii_s[e0 + e] * FF;
        const size_t rj = (size_t)jj_s[e0 + e] * FF;
        float4 qa = *(const float4*)&g_q[ri + f0];
        float4 qb = *(const float4*)&g_q[ri + f0 + 112];
        float4 ka = *(const float4*)&g_k[rj + f0];
        float4 kb = *(const float4*)&g_k[rj + f0 + 112];
        float aA = a0 * (qa.x * ka.x);
        aA = fmaf(a1, qa.y * ka.y, aA);
        aA = fmaf(a2, qa.z * ka.z, aA);
        aA = fmaf(a3, qa.w * ka.w, aA);
        float aB = a4 * (qb.x * kb.x);
        aB = fmaf(a5, qb.y * kb.y, aB);
        aB = fmaf(a6, qb.z * kb.z, aB);
        aB = fmaf(a7, qb.w * kb.w, aB);
        atomicAdd(&alpha_s[e0 + e][hA], aA);
        atomicAdd(&alpha_s[e0 + e][hB], aB);
    }
    __syncthreads();

    // ---- scatter x_att: thread f owns output column f; run-length aggregate over sorted i
    {
        int f = tid;                 // 0..223
        int hh = f / DV;             // 0..3
        float run = 0.f;
        int iprev = ii_s[0];
#pragma unroll 4
        for (int e = 0; e < EPB; e++) {
            int i = ii_s[e];
            if (i != iprev) {
                atomicAdd(&out_x[(size_t)iprev * FF + f], run);
                run = 0.f; iprev = i;
            }
            float a = alpha_s[e][hh] * cut_s[e];
            run = fmaf(a, __ldg(&g_v[(size_t)jj_s[e] * FF + f]), run);
        }
        atomicAdd(&out_x[(size_t)iprev * FF + f], run);
    }
    // ---- scatter ev_att
    if (tid < NORD) {
        int o  = tid;
        int hh = (o < 3) ? 4 : ((o < 8) ? 5 : 6);
        float run = 0.f;
        int iprev = ii_s[0];
        for (int e = 0; e < EPB; e++) {
            int i = ii_s[e];
            if (i != iprev) {
                atomicAdd(&out_ev[(size_t)iprev * NORD + o], run);
                run = 0.f; iprev = i;
            }
            run = fmaf(alpha_s[e][hh] * cut_s[e], ylm_s[e][o], run);
        }
        atomicAdd(&out_ev[(size_t)iprev * NORD + o], run);
    }
}

extern "C" void kernel_launch(void* const* d_in, const int* in_sizes, int n_in,
                              void* d_out, int out_size) {
    const float* x     = (const float*)d_in[0];
    const float* ev    = (const float*)d_in[1];
    const float* rbf   = (const float*)d_in[2];
    const float* ylm   = (const float*)d_in[3];
    const float* cut   = (const float*)d_in[4];
    const int*   idx_i = (const int*)d_in[5];
    const int*   idx_j = (const int*)d_in[6];
    const float* W1r   = (const float*)d_in[7];
    const float* b1r   = (const float*)d_in[8];
    const float* W2r   = (const float*)d_in[9];
    const float* b2r   = (const float*)d_in[10];
    const float* W1s   = (const float*)d_in[11];
    const float* b1s   = (const float*)d_in[12];
    const float* W2s   = (const float*)d_in[13];
    const float* b2s   = (const float*)d_in[14];
    const float* Wq    = (const float*)d_in[15];
    const float* Wk    = (const float*)d_in[16];
    const float* Wv    = (const float*)d_in[17];

    float* out    = (float*)d_out;
    float* out_x  = out;                       // [N,224]
    float* out_ev = out + (size_t)NN * FF;     // [N,15]

    const int dynsmem = (FF * HP) * (int)sizeof(float);   // 32256 B
    cudaFuncSetAttribute(edge_kernel, cudaFuncAttributeMaxDynamicSharedMemorySize, dynsmem);

    // 1) per-node q,k,v + zero outputs
    node_kernel<<<NN, 224>>>(x, Wq, Wk, Wv, out_x, out_ev);

    // 2) edges
    edge_kernel<<<PP / EPB, TPB, dynsmem>>>(
        rbf, ylm, cut, idx_i, idx_j, ev,
        W1r, b1r, W2r, b2r, W1s, b1s, W2s, b2s,
        out_x, out_ev);
}